// round 2
// baseline (speedup 1.0000x reference)
#include <cuda_runtime.h>
#include <cstdint>

#define T_FRAMES 2000
#define BATCH    64
#define CHANS    256
#define TLEN     200
#define NEG_INF  (-1e30f)
#define STAGES   8

// Scratch (static __device__ arrays: allocation-guard safe)
__device__ float g_lse_tr[BATCH * T_FRAMES];   // [b][t] transposed for DP-kernel reads
__device__ float g_loss[BATCH];

// ---------------- Kernel A: per-(t,b) logsumexp over C=256 ----------------
// 8 warps/block, one warp per row. Reads the full 131MB input once.
__global__ __launch_bounds__(256) void lse_kernel(const float* __restrict__ inp) {
    int warp = threadIdx.x >> 5;
    int lane = threadIdx.x & 31;
    int r = blockIdx.x * 8 + warp;               // r = t*BATCH + b
    const float4* base = reinterpret_cast<const float4*>(inp + (size_t)r * CHANS);
    float4 a = base[lane];
    float4 c = base[lane + 32];
    float m = fmaxf(fmaxf(fmaxf(a.x, a.y), fmaxf(a.z, a.w)),
                    fmaxf(fmaxf(c.x, c.y), fmaxf(c.z, c.w)));
    #pragma unroll
    for (int o = 16; o; o >>= 1) m = fmaxf(m, __shfl_xor_sync(0xffffffffu, m, o));
    float s = __expf(a.x - m) + __expf(a.y - m) + __expf(a.z - m) + __expf(a.w - m)
            + __expf(c.x - m) + __expf(c.y - m) + __expf(c.z - m) + __expf(c.w - m);
    #pragma unroll
    for (int o = 16; o; o >>= 1) s += __shfl_xor_sync(0xffffffffu, s, o);
    if (lane == 0) {
        int t = r >> 6;            // BATCH = 64
        int b = r & 63;
        g_lse_tr[b * T_FRAMES + t] = m + __logf(s);
    }
}

// ---------------- Kernel B: forward DP, one warp per batch element ----------------
__device__ __forceinline__ void cp16(uint32_t s, const void* g) {
    asm volatile("cp.async.cg.shared.global [%0], [%1], 16;" :: "r"(s), "l"(g));
}
__device__ __forceinline__ float lae(float a, float b) {
    // logaddexp. Works for NEG_INF sentinels: d huge -> expf -> 0 -> +log(1)=0.
    float m = fmaxf(a, b);
    float d = fabsf(a - b);
    return m + __logf(1.0f + __expf(-d));
}

__global__ __launch_bounds__(32) void dp_kernel(const float* __restrict__ inp,
                                                const unsigned* __restrict__ tgtw) {
    __shared__ __align__(16) float rows[STAGES][CHANS];
    const int lane = threadIdx.x;
    const int b = blockIdx.x;

    const char* colbase = (const char*)(inp + (size_t)b * CHANS);
    const size_t row_stride = (size_t)BATCH * CHANS * sizeof(float);
    uint32_t sbase = (uint32_t)__cvta_generic_to_shared(&rows[0][0]);
    uint32_t soff = lane * 32;                      // 32B per lane per row

    // Prologue: prefetch rows 0..7, one commit group per row (group g == row g).
    #pragma unroll
    for (int s = 0; s < STAGES; s++) {
        const char* g = colbase + (size_t)s * row_stride + soff;
        uint32_t sa = sbase + s * (CHANS * 4) + soff;
        cp16(sa, g); cp16(sa + 16, g + 16);
        asm volatile("cp.async.commit_group;");
    }

    // ---- Target dtype auto-detect (JAX default disables x64 -> int32 likely).
    // Read only the first 512 32-bit words (in-bounds for either dtype: int32
    // buffer has 12800 words, int64 has 25600). If the buffer is little-endian
    // int64 with values < 2^32, every odd word is 0. If int32, odd words are
    // random tokens in [0,256) -> OR over 256 samples is ~surely nonzero.
    unsigned orv = 0;
    for (int i = lane * 2 + 1; i < 512; i += 64) orv |= tgtw[i];
    #pragma unroll
    for (int o = 16; o; o >>= 1) orv |= __shfl_xor_sync(0xffffffffu, orv, o);
    const int wstride = (orv == 0) ? 2 : 1;   // int64 -> low word at index 2*i

    // Per-lane target indices: lane owns l = lane*7 .. lane*7+6 (clamped padding)
    int idx[7];
    #pragma unroll
    for (int j = 0; j < 7; j++) {
        int l = lane * 7 + j;
        if (l > TLEN - 1) l = TLEN - 1;
        idx[j] = (int)tgtw[(b * TLEN + l) * wstride];
    }

    asm volatile("cp.async.wait_group 7;");  // row 0 ready
    __syncwarp();

    float beta[7];
    #pragma unroll
    for (int j = 0; j < 7; j++) beta[j] = NEG_INF;
    if (lane == 0) beta[0] = rows[0][idx[0]];   // beta_0[0] = raw logit of target[0]
    __syncwarp();

    // refill stage 0 with row 8 (commit group 8)
    {
        const char* g = colbase + (size_t)STAGES * row_stride + soff;
        uint32_t sa = sbase + soff;
        cp16(sa, g); cp16(sa + 16, g + 16);
        asm volatile("cp.async.commit_group;");
    }

    for (int t = 1; t < T_FRAMES; t++) {
        // At top of iter t: committed groups 0..t+7, wait_group 7 -> group t (row t) done.
        asm volatile("cp.async.wait_group 7;");
        __syncwarp();
        const float* row = rows[t & (STAGES - 1)];
        float e[7];
        #pragma unroll
        for (int j = 0; j < 7; j++) e[j] = row[idx[j]];
        __syncwarp();   // all lanes done reading this stage before overwrite

        int tp = t + STAGES;
        if (tp < T_FRAMES) {
            const char* g = colbase + (size_t)tp * row_stride + soff;
            uint32_t sa = sbase + (t & (STAGES - 1)) * (CHANS * 4) + soff;
            cp16(sa, g); cp16(sa + 16, g + 16);
        }
        asm volatile("cp.async.commit_group;");  // always commit: keep group==row accounting

        float prev = __shfl_up_sync(0xffffffffu, beta[6], 1);
        if (lane == 0) prev = NEG_INF;
        float nb[7];
        nb[0] = e[0] + lae(beta[0], prev);
        #pragma unroll
        for (int j = 1; j < 7; j++) nb[j] = e[j] + lae(beta[j], beta[j - 1]);
        #pragma unroll
        for (int j = 0; j < 7; j++) beta[j] = nb[j];
    }

    // l = 199 lives at lane 28, slot 3 (28*7+3)
    float b199 = __shfl_sync(0xffffffffu, beta[3], 28);

    // sum of lse over t for this b (deferred normalization)
    const float* lseb = g_lse_tr + b * T_FRAMES;
    float s = 0.0f;
    #pragma unroll 4
    for (int i = lane; i < T_FRAMES; i += 32) s += lseb[i];
    #pragma unroll
    for (int o = 16; o; o >>= 1) s += __shfl_xor_sync(0xffffffffu, s, o);
    if (lane == 0) g_loss[b] = s - b199;     // loss_b = sum(lse) - beta_T[L-1]
}

// ---------------- Kernel C: mean over batch ----------------
__global__ void final_kernel(float* __restrict__ out) {
    int lane = threadIdx.x;
    float v = g_loss[lane] + g_loss[lane + 32];
    #pragma unroll
    for (int o = 16; o; o >>= 1) v += __shfl_xor_sync(0xffffffffu, v, o);
    if (lane == 0) out[0] = v * (1.0f / BATCH);
}

extern "C" void kernel_launch(void* const* d_in, const int* in_sizes, int n_in,
                              void* d_out, int out_size) {
    const float* inp = (const float*)d_in[0];           // [T, B, C] fp32
    const unsigned* tgt = (const unsigned*)d_in[1];     // [B, L] int32 or int64 (auto-detected)
    lse_kernel<<<(T_FRAMES * BATCH) / 8, 256>>>(inp);
    dp_kernel<<<BATCH, 32>>>(inp, tgt);
    final_kernel<<<1, 32>>>((float*)d_out);
}

// round 3
// speedup vs baseline: 1.0709x; 1.0709x over previous
#include <cuda_runtime.h>
#include <cuda_fp16.h>
#include <cstdint>

#define T_FRAMES 2000
#define BATCH    64
#define CHANS    256
#define TLEN     200
#define STAGES   8
#define LN2      0.69314718055994530942f

// Scratch (__device__ globals: allocation-guard safe)
__device__ float g_lse_tr[BATCH * T_FRAMES];        // [b][t]
__device__ float g_loss[BATCH];
__device__ int   g_tgt[BATCH * 256];                // [b][lane*8+j], padded/clamped
__device__ uint4 g_E[BATCH * T_FRAMES * 32];        // [b][t] rows of 256 fp16 = 512B (65.5MB)

// ---------------- Kernel 0: target prep (dtype detect + pad/transpose) ----------------
__global__ void prep_tgt(const unsigned* __restrict__ tgtw) {
    // JAX x64-off => int32 targets; detect int64 by OR of odd 32-bit words.
    unsigned orv = 0;
    for (int i = 1; i < 512; i += 2) orv |= tgtw[i];
    int ws = (orv == 0) ? 2 : 1;
    for (int k = threadIdx.x; k < BATCH * 256; k += 256) {
        int b = k >> 8, s = k & 255;
        int l = (s >> 3) * 7 + (s & 7);
        if (l > TLEN - 1) l = TLEN - 1;
        g_tgt[k] = (int)tgtw[(b * TLEN + l) * ws];
    }
}

// ---------------- Kernel 1: fused lse + gather + exp (fp16) ----------------
__global__ __launch_bounds__(256) void gather_lse(const float* __restrict__ inp) {
    __shared__ float sm[8][CHANS];
    int warp = threadIdx.x >> 5;
    int lane = threadIdx.x & 31;
    int r = blockIdx.x * 8 + warp;                 // r = t*BATCH + b
    const float4* base = reinterpret_cast<const float4*>(inp + (size_t)r * CHANS);
    float4 a = base[lane];
    float4 c = base[lane + 32];

    float mx = fmaxf(fmaxf(fmaxf(a.x, a.y), fmaxf(a.z, a.w)),
                     fmaxf(fmaxf(c.x, c.y), fmaxf(c.z, c.w)));
    #pragma unroll
    for (int o = 16; o; o >>= 1) mx = fmaxf(mx, __shfl_xor_sync(0xffffffffu, mx, o));
    float sv = __expf(a.x - mx) + __expf(a.y - mx) + __expf(a.z - mx) + __expf(a.w - mx)
             + __expf(c.x - mx) + __expf(c.y - mx) + __expf(c.z - mx) + __expf(c.w - mx);
    #pragma unroll
    for (int o = 16; o; o >>= 1) sv += __shfl_xor_sync(0xffffffffu, sv, o);

    int t = r >> 6;                                // BATCH = 64
    int b = r & 63;
    if (lane == 0) g_lse_tr[b * T_FRAMES + t] = mx + __logf(sv);

    // stage row to smem, then gather target channels
    reinterpret_cast<float4*>(sm[warp])[lane] = a;
    reinterpret_cast<float4*>(sm[warp])[lane + 32] = c;
    __syncwarp();

    const int4* tg = reinterpret_cast<const int4*>(g_tgt + b * 256);
    int4 i0 = tg[lane * 2];
    int4 i1 = tg[lane * 2 + 1];
    const float* row = sm[warp];
    float e0 = __expf(row[i0.x]) * 0.5f;
    float e1 = __expf(row[i0.y]) * 0.5f;
    float e2 = __expf(row[i0.z]) * 0.5f;
    float e3 = __expf(row[i0.w]) * 0.5f;
    float e4 = __expf(row[i1.x]) * 0.5f;
    float e5 = __expf(row[i1.y]) * 0.5f;
    float e6 = __expf(row[i1.z]) * 0.5f;
    float e7 = __expf(row[i1.w]) * 0.5f;

    __half2 h01 = __floats2half2_rn(e0, e1);
    __half2 h23 = __floats2half2_rn(e2, e3);
    __half2 h45 = __floats2half2_rn(e4, e5);
    __half2 h67 = __floats2half2_rn(e6, e7);
    uint4 pack;
    pack.x = *reinterpret_cast<unsigned*>(&h01);
    pack.y = *reinterpret_cast<unsigned*>(&h23);
    pack.z = *reinterpret_cast<unsigned*>(&h45);
    pack.w = *reinterpret_cast<unsigned*>(&h67);
    g_E[(size_t)(b * T_FRAMES + t) * 32 + lane] = pack;
}

// ---------------- Kernel 2: forward DP, linear domain, lane-local scales ----------------
__device__ __forceinline__ void cp16(uint32_t s, const void* g) {
    asm volatile("cp.async.cg.shared.global [%0], [%1], 16;" :: "r"(s), "l"(g));
}

__global__ __launch_bounds__(32) void dp_kernel() {
    __shared__ __align__(16) uint4 ring[STAGES * 32];
    const int lane = threadIdx.x;
    const int b = blockIdx.x;

    const char* gbase = (const char*)(g_E + (size_t)b * T_FRAMES * 32);
    uint32_t sb = (uint32_t)__cvta_generic_to_shared(ring);
    uint32_t soff = lane * 16;

    #pragma unroll
    for (int s = 0; s < STAGES; s++) {
        cp16(sb + s * 512 + soff, gbase + (size_t)s * 512 + soff);
        asm volatile("cp.async.commit_group;");
    }

    asm volatile("cp.async.wait_group 7;");
    __syncwarp();

    // init from row 0: p[0] (lane 0) = E'(t=0, l=0)
    uint4 v0 = ring[lane];
    __half2 h0 = *reinterpret_cast<__half2*>(&v0.x);
    float2 f01i = __half22float2(h0);
    float p0 = (lane == 0) ? f01i.x : 0.0f;
    float p1 = 0.f, p2 = 0.f, p3 = 0.f, p4 = 0.f, p5 = 0.f, p6 = 0.f;
    int   X = 0;
    float f = 0.0f;

    // refill stage 0 with row 8
    cp16(sb + soff, gbase + (size_t)STAGES * 512 + soff);
    asm volatile("cp.async.commit_group;");

    for (int t = 1; t < T_FRAMES; t++) {
        asm volatile("cp.async.wait_group 7;");
        uint4 v = ring[(t & (STAGES - 1)) * 32 + lane];
        __half2 h01 = *reinterpret_cast<__half2*>(&v.x);
        __half2 h23 = *reinterpret_cast<__half2*>(&v.y);
        __half2 h45 = *reinterpret_cast<__half2*>(&v.z);
        __half2 h67 = *reinterpret_cast<__half2*>(&v.w);
        float2 e01 = __half22float2(h01);
        float2 e23 = __half22float2(h23);
        float2 e45 = __half22float2(h45);
        float2 e67 = __half22float2(h67);

        int tp = t + STAGES;
        if (tp < T_FRAMES) {
            cp16(sb + (t & (STAGES - 1)) * 512 + soff, gbase + (size_t)tp * 512 + soff);
        }
        asm volatile("cp.async.commit_group;");

        if ((t & 3) == 1) {
            // lane-local renorm (exact power-of-2 rescale) + cross-lane scale factor
            float m = fmaxf(fmaxf(fmaxf(p0, p1), fmaxf(p2, p3)),
                            fmaxf(fmaxf(p4, p5), p6));
            float m2 = fmaxf(m, 1.17549435e-38f);
            int k = ((__float_as_int(m2) >> 23) & 255) - 127;
            int Xl = X + k;
            int Xp = __shfl_up_sync(0xffffffffu, Xl, 1);
            int d0 = (lane == 0) ? 0 : (Xp - Xl);
            int extra = d0 > 60 ? (d0 - 60) : 0;        // swamped-lane clamp (exact)
            X = Xl + extra;
            int d = d0 - extra;                          // <= 60
            if (d < -127) d = -127;
            float fn = __int_as_float((127 + d) << 23);  // d=-127 -> 0.0f
            f = (lane == 0) ? 0.0f : fn;
            int ex = -(k + extra);                       // <= 126 always
            float psc = (ex < -126) ? 0.0f : __int_as_float((127 + ex) << 23);
            p0 *= psc; p1 *= psc; p2 *= psc; p3 *= psc;
            p4 *= psc; p5 *= psc; p6 *= psc;
        }

        float pin = __shfl_up_sync(0xffffffffu, p6, 1) * f;
        float n0 = e01.x * (p0 + pin);
        float n1 = e01.y * (p1 + p0);
        float n2 = e23.x * (p2 + p1);
        float n3 = e23.y * (p3 + p2);
        float n4 = e45.x * (p4 + p3);
        float n5 = e45.y * (p5 + p4);
        float n6 = e67.x * (p6 + p5);
        p0 = n0; p1 = n1; p2 = n2; p3 = n3; p4 = n4; p5 = n5; p6 = n6;
    }

    // l=199 lives at lane 28, slot 3; undo the 2^-1 pre-scale (2000 factors)
    float p199 = __shfl_sync(0xffffffffu, p3, 28);
    int   X199 = __shfl_sync(0xffffffffu, X, 28);
    float beta199 = __logf(p199) + (float)X199 * LN2 + (float)T_FRAMES * LN2;

    const float* lseb = g_lse_tr + b * T_FRAMES;
    float s = 0.0f;
    #pragma unroll 4
    for (int i = lane; i < T_FRAMES; i += 32) s += lseb[i];
    #pragma unroll
    for (int o = 16; o; o >>= 1) s += __shfl_xor_sync(0xffffffffu, s, o);
    if (lane == 0) g_loss[b] = s - beta199;
}

// ---------------- Kernel 3: mean over batch ----------------
__global__ void final_kernel(float* __restrict__ out) {
    int lane = threadIdx.x;
    float v = g_loss[lane] + g_loss[lane + 32];
    #pragma unroll
    for (int o = 16; o; o >>= 1) v += __shfl_xor_sync(0xffffffffu, v, o);
    if (lane == 0) out[0] = v * (1.0f / BATCH);
}

extern "C" void kernel_launch(void* const* d_in, const int* in_sizes, int n_in,
                              void* d_out, int out_size) {
    const float* inp = (const float*)d_in[0];        // [T, B, C] fp32
    const unsigned* tgt = (const unsigned*)d_in[1];  // [B, L] int32/int64 auto
    prep_tgt<<<1, 256>>>(tgt);
    gather_lse<<<(T_FRAMES * BATCH) / 8, 256>>>(inp);
    dp_kernel<<<BATCH, 32>>>();
    final_kernel<<<1, 32>>>((float*)d_out);
}

// round 4
// speedup vs baseline: 1.8857x; 1.7609x over previous
#include <cuda_runtime.h>
#include <cuda_fp16.h>
#include <cstdint>

#define T_FRAMES 2000
#define BATCH    64
#define CHANS    256
#define TLEN     200
#define RING     32
#define LN2      0.69314718055994530942f

// Scratch (__device__ globals: allocation-guard safe)
__device__ float g_lse_tr[BATCH * T_FRAMES];                 // [b][t]
__device__ float g_loss[BATCH];
__device__ uint4 g_E[(size_t)BATCH * T_FRAMES * 32];         // fp16 rows, 512B each (65.5MB)

__device__ __forceinline__ void cp16(uint32_t s, const void* g) {
    asm volatile("cp.async.cg.shared.global [%0], [%1], 16;" :: "r"(s), "l"(g));
}

// ---------------- Kernel 1: fused target-prep + lse + gather + exp(fp16) ----------------
__global__ __launch_bounds__(256) void gather_lse(const float* __restrict__ inp,
                                                  const unsigned* __restrict__ tgtw) {
    __shared__ float sm[8][CHANS];
    int warp = threadIdx.x >> 5, lane = threadIdx.x & 31;
    int r = blockIdx.x * 8 + warp;               // r = t*BATCH + b
    int t = r >> 6, b = r & 63;

    const float4* base = reinterpret_cast<const float4*>(inp + (size_t)r * CHANS);
    float4 a = base[lane];
    float4 c = base[lane + 32];

    // Target dtype auto-detect (JAX x64-off => int32). OR of odd 32-bit words
    // over first 512 words: zero iff little-endian int64 with small values.
    unsigned orv = 0;
    #pragma unroll
    for (int k = 0; k < 8; k++) orv |= tgtw[lane * 2 + 1 + k * 64];
    #pragma unroll
    for (int o = 16; o; o >>= 1) orv |= __shfl_xor_sync(~0u, orv, o);
    int ws = (orv == 0) ? 2 : 1;

    float mx = fmaxf(fmaxf(fmaxf(a.x, a.y), fmaxf(a.z, a.w)),
                     fmaxf(fmaxf(c.x, c.y), fmaxf(c.z, c.w)));
    #pragma unroll
    for (int o = 16; o; o >>= 1) mx = fmaxf(mx, __shfl_xor_sync(~0u, mx, o));
    float sv = __expf(a.x - mx) + __expf(a.y - mx) + __expf(a.z - mx) + __expf(a.w - mx)
             + __expf(c.x - mx) + __expf(c.y - mx) + __expf(c.z - mx) + __expf(c.w - mx);
    #pragma unroll
    for (int o = 16; o; o >>= 1) sv += __shfl_xor_sync(~0u, sv, o);
    if (lane == 0) g_lse_tr[b * T_FRAMES + t] = mx + __logf(sv);

    reinterpret_cast<float4*>(sm[warp])[lane]      = a;
    reinterpret_cast<float4*>(sm[warp])[lane + 32] = c;
    __syncwarp();

    const float* row = sm[warp];
    float e[8];
    #pragma unroll
    for (int j = 0; j < 8; j++) {
        int l = lane * 7 + j;                    // slot 7 is padding (unused in DP)
        if (l > TLEN - 1) l = TLEN - 1;
        int ix = (int)tgtw[(b * TLEN + l) * ws];
        e[j] = __expf(row[ix]) * 0.5f;           // E' = exp(logit)/2
    }
    __half2 h0 = __floats2half2_rn(e[0], e[1]);
    __half2 h1 = __floats2half2_rn(e[2], e[3]);
    __half2 h2 = __floats2half2_rn(e[4], e[5]);
    __half2 h3 = __floats2half2_rn(e[6], e[7]);
    uint4 pk;
    pk.x = *reinterpret_cast<unsigned*>(&h0);
    pk.y = *reinterpret_cast<unsigned*>(&h1);
    pk.z = *reinterpret_cast<unsigned*>(&h2);
    pk.w = *reinterpret_cast<unsigned*>(&h3);
    g_E[(size_t)(b * T_FRAMES + t) * 32 + lane] = pk;
}

// ---------------- Kernel 2: forward DP, linear domain, unroll-8, lane-local scales ----------------
__global__ __launch_bounds__(32) void dp_kernel() {
    __shared__ __align__(16) uint4 ring[RING * 32];          // 16KB
    const int lane = threadIdx.x;
    const int b = blockIdx.x;
    const char* gb = (const char*)(g_E + (size_t)b * T_FRAMES * 32);
    uint32_t sb = (uint32_t)__cvta_generic_to_shared(ring);
    uint32_t so = lane * 16;

    // Prologue: rows 0..31, one commit group per 4 rows (8 groups).
    #pragma unroll
    for (int g = 0; g < 8; g++) {
        #pragma unroll
        for (int rr = 0; rr < 4; rr++) {
            int rw = g * 4 + rr;
            cp16(sb + rw * 512 + so, gb + (size_t)rw * 512 + so);
        }
        asm volatile("cp.async.commit_group;");
    }
    asm volatile("cp.async.wait_group 0;");
    __syncwarp();

    float p0, p1, p2, p3, p4, p5, p6;
    {
        uint4 v = ring[lane];
        float2 ff = __half22float2(*reinterpret_cast<__half2*>(&v.x));
        p0 = (lane == 0) ? ff.x : 0.0f;
    }
    p1 = p2 = p3 = p4 = p5 = p6 = 0.0f;
    int   X = 0;
    float f = (lane == 0) ? 0.0f : 1.0f;   // all scales equal initially -> factor 1

    // Peel t = 1..7 (no renorm needed: growth bounded by 2^~55)
    #pragma unroll
    for (int t = 1; t < 8; t++) {
        uint4 v = ring[t * 32 + lane];
        float2 e01 = __half22float2(*reinterpret_cast<__half2*>(&v.x));
        float2 e23 = __half22float2(*reinterpret_cast<__half2*>(&v.y));
        float2 e45 = __half22float2(*reinterpret_cast<__half2*>(&v.z));
        float2 e67 = __half22float2(*reinterpret_cast<__half2*>(&v.w));
        float pin = __shfl_up_sync(~0u, p6, 1) * f;
        float n0 = e01.x * (p0 + pin);
        float n1 = e01.y * (p1 + p0);
        float n2 = e23.x * (p2 + p1);
        float n3 = e23.y * (p3 + p2);
        float n4 = e45.x * (p4 + p3);
        float n5 = e45.y * (p5 + p4);
        float n6 = e67.x * (p6 + p5);
        p0 = n0; p1 = n1; p2 = n2; p3 = n3; p4 = n4; p5 = n5; p6 = n6;
    }

    // Main: blocks of 8 frames. One wait_group + one renorm per block.
    for (int tb = 8; tb < T_FRAMES; tb += 8) {
        // Prefetch rows tb+24 .. tb+31 (2 groups; always commit to keep accounting)
        #pragma unroll
        for (int g = 0; g < 2; g++) {
            #pragma unroll
            for (int rr = 0; rr < 4; rr++) {
                int rw = tb + 24 + g * 4 + rr;
                if (rw < T_FRAMES)
                    cp16(sb + (rw & (RING - 1)) * 512 + so, gb + (size_t)rw * 512 + so);
            }
            asm volatile("cp.async.commit_group;");
        }
        // <=6 pending of last 8 groups -> rows tb..tb+7 complete (issued 3 blocks ago)
        asm volatile("cp.async.wait_group 6;");
        __syncwarp();

        // Lane-local renorm (exact power-of-2) + cross-lane factor. Period 8, clamp 2^40.
        {
            float m  = fmaxf(fmaxf(fmaxf(p0, p1), fmaxf(p2, p3)),
                             fmaxf(fmaxf(p4, p5), p6));
            float m2 = fmaxf(m, 1.17549435e-38f);
            int k  = ((__float_as_int(m2) >> 23) & 255) - 127;
            int Xl = X + k;
            int Xp = __shfl_up_sync(~0u, Xl, 1);
            int d0 = (lane == 0) ? 0 : (Xp - Xl);
            int extra = d0 > 40 ? (d0 - 40) : 0;      // swamped-lane clamp (exact rescale)
            X = Xl + extra;
            int d = d0 - extra;                        // <= 40
            if (d < -127) d = -127;
            float fn = __int_as_float((127 + d) << 23);   // d=-127 -> 0.0f
            f = (lane == 0) ? 0.0f : fn;
            int ex = -(k + extra);
            float psc = (ex < -126) ? 0.0f : __int_as_float((127 + ex) << 23);
            p0 *= psc; p1 *= psc; p2 *= psc; p3 *= psc;
            p4 *= psc; p5 *= psc; p6 *= psc;
        }

        int rbase = (tb & (RING - 1)) * 32 + lane;   // no wrap within a block of 8
        #pragma unroll
        for (int u = 0; u < 8; u++) {
            uint4 v = ring[rbase + u * 32];
            float2 e01 = __half22float2(*reinterpret_cast<__half2*>(&v.x));
            float2 e23 = __half22float2(*reinterpret_cast<__half2*>(&v.y));
            float2 e45 = __half22float2(*reinterpret_cast<__half2*>(&v.z));
            float2 e67 = __half22float2(*reinterpret_cast<__half2*>(&v.w));
            float pin = __shfl_up_sync(~0u, p6, 1) * f;
            float n0 = e01.x * (p0 + pin);
            float n1 = e01.y * (p1 + p0);
            float n2 = e23.x * (p2 + p1);
            float n3 = e23.y * (p3 + p2);
            float n4 = e45.x * (p4 + p3);
            float n5 = e45.y * (p5 + p4);
            float n6 = e67.x * (p6 + p5);
            p0 = n0; p1 = n1; p2 = n2; p3 = n3; p4 = n4; p5 = n5; p6 = n6;
        }
    }

    // l=199 lives at lane 28, slot 3. Undo the 2000 implicit /2 factors.
    float p199 = __shfl_sync(~0u, p3, 28);
    int   X199 = __shfl_sync(~0u, X, 28);
    float beta199 = __logf(p199) + (float)X199 * LN2 + (float)T_FRAMES * LN2;

    const float* lseb = g_lse_tr + b * T_FRAMES;
    float s = 0.0f;
    #pragma unroll 4
    for (int i = lane; i < T_FRAMES; i += 32) s += lseb[i];
    #pragma unroll
    for (int o = 16; o; o >>= 1) s += __shfl_xor_sync(~0u, s, o);
    if (lane == 0) g_loss[b] = s - beta199;
}

// ---------------- Kernel 3: mean over batch ----------------
__global__ void final_kernel(float* __restrict__ out) {
    int lane = threadIdx.x;
    float v = g_loss[lane] + g_loss[lane + 32];
    #pragma unroll
    for (int o = 16; o; o >>= 1) v += __shfl_xor_sync(~0u, v, o);
    if (lane == 0) out[0] = v * (1.0f / BATCH);
}

extern "C" void kernel_launch(void* const* d_in, const int* in_sizes, int n_in,
                              void* d_out, int out_size) {
    const float* inp = (const float*)d_in[0];        // [T, B, C] fp32
    const unsigned* tgt = (const unsigned*)d_in[1];  // [B, L] int32/int64 auto
    gather_lse<<<(T_FRAMES * BATCH) / 8, 256>>>(inp, tgt);
    dp_kernel<<<BATCH, 32>>>();
    final_kernel<<<1, 32>>>((float*)d_out);
}